// round 1
// baseline (speedup 1.0000x reference)
#include <cuda_runtime.h>
#include <cuda_bf16.h>
#include <cstdint>

// ---------------------------------------------------------------------------
// SparseResBlock3D:
//   film        = silu(emb) @ emb_W + emb_b      (B=4 x 256, split scale/shift)
//   h1          = silu(LN(feats; g,b))
//   h2          = sparse_conv27(h1, W1) + b1
//   h3          = silu(LN(h2) * (1+scale[bidx]) + shift[bidx])
//   out         = sparse_conv27(h3, W2) + b2 + feats
//
// Shapes: N=200000, C=COUT=128, 27 taps, W layout (27, C, COUT) row-major.
// ---------------------------------------------------------------------------

#define NROWS   200000
#define C       128
#define TAPS    27
#define TM      64           // rows per conv block
#define GPITCH  132          // padded smem pitch for gather tile (floats)

// Scratch (static device globals — no runtime allocation)
__device__ float g_bufA[(size_t)NROWS * C];
__device__ float g_bufB[(size_t)NROWS * C];
__device__ float g_film[4 * 256];   // [b][0:128]=1+scale, [b][128:256]=shift

__device__ __forceinline__ float silu_f(float x) {
    return x / (1.0f + expf(-x));
}

// ---------------------------------------------------------------------------
// Kernel 1: FiLM embedding GEMM.  grid=(B), block=256.
// ---------------------------------------------------------------------------
__global__ void film_kernel(const float* __restrict__ emb,
                            const float* __restrict__ embW,
                            const float* __restrict__ embb) {
    __shared__ float s[512];
    int b = blockIdx.x;
    int c = threadIdx.x;
    for (int e = c; e < 512; e += 256) {
        float v = emb[b * 512 + e];
        s[e] = silu_f(v);
    }
    __syncthreads();
    float acc = embb[c];
#pragma unroll 8
    for (int e = 0; e < 512; ++e) {
        acc = fmaf(s[e], embW[e * 256 + c], acc);
    }
    g_film[b * 256 + c] = (c < 128) ? (1.0f + acc) : acc;
}

// ---------------------------------------------------------------------------
// Kernel 2: LN(gamma,beta) + SiLU  -> g_bufA.  One warp per row (C=128).
// grid = N/8, block = 256 (8 warps).
// ---------------------------------------------------------------------------
__global__ void ln_silu_kernel(const float* __restrict__ x,
                               const float* __restrict__ gamma,
                               const float* __restrict__ beta) {
    int row  = blockIdx.x * 8 + (threadIdx.x >> 5);
    int lane = threadIdx.x & 31;
    const float4* xr = reinterpret_cast<const float4*>(x + (size_t)row * C);
    float4 v = xr[lane];
    float s  = v.x + v.y + v.z + v.w;
    float ss = v.x * v.x + v.y * v.y + v.z * v.z + v.w * v.w;
#pragma unroll
    for (int o = 16; o > 0; o >>= 1) {
        s  += __shfl_xor_sync(0xffffffffu, s, o);
        ss += __shfl_xor_sync(0xffffffffu, ss, o);
    }
    float mu  = s * (1.0f / 128.0f);
    float var = ss * (1.0f / 128.0f) - mu * mu;
    float inv = rsqrtf(var + 1e-6f);
    float4 g  = reinterpret_cast<const float4*>(gamma)[lane];
    float4 be = reinterpret_cast<const float4*>(beta)[lane];
    float4 y;
    y.x = silu_f((v.x - mu) * inv * g.x + be.x);
    y.y = silu_f((v.y - mu) * inv * g.y + be.y);
    y.z = silu_f((v.z - mu) * inv * g.z + be.z);
    y.w = silu_f((v.w - mu) * inv * g.w + be.w);
    reinterpret_cast<float4*>(g_bufA + (size_t)row * C)[lane] = y;
}

// ---------------------------------------------------------------------------
// Kernel 4: LN(no affine) + FiLM + SiLU : g_bufB -> g_bufA.
// ---------------------------------------------------------------------------
__global__ void ln_film_silu_kernel(const int* __restrict__ batch_idx) {
    int row  = blockIdx.x * 8 + (threadIdx.x >> 5);
    int lane = threadIdx.x & 31;
    const float4* xr = reinterpret_cast<const float4*>(g_bufB + (size_t)row * C);
    float4 v = xr[lane];
    float s  = v.x + v.y + v.z + v.w;
    float ss = v.x * v.x + v.y * v.y + v.z * v.z + v.w * v.w;
#pragma unroll
    for (int o = 16; o > 0; o >>= 1) {
        s  += __shfl_xor_sync(0xffffffffu, s, o);
        ss += __shfl_xor_sync(0xffffffffu, ss, o);
    }
    float mu  = s * (1.0f / 128.0f);
    float var = ss * (1.0f / 128.0f) - mu * mu;
    float inv = rsqrtf(var + 1e-6f);
    int b = batch_idx[row];
    float4 sc = *reinterpret_cast<const float4*>(&g_film[b * 256 + lane * 4]);
    float4 sh = *reinterpret_cast<const float4*>(&g_film[b * 256 + 128 + lane * 4]);
    float4 y;
    y.x = silu_f((v.x - mu) * inv * sc.x + sh.x);
    y.y = silu_f((v.y - mu) * inv * sc.y + sh.y);
    y.z = silu_f((v.z - mu) * inv * sc.z + sh.z);
    y.w = silu_f((v.w - mu) * inv * sc.w + sh.w);
    reinterpret_cast<float4*>(g_bufA + (size_t)row * C)[lane] = y;
}

// ---------------------------------------------------------------------------
// Sparse 27-tap conv: out[i,c] = sum_k sum_j gather_k(src)[i,j] * W[k,j,c] (+bias)
// Block: 256 threads, 64 rows x 128 cols tile. Per-thread 4x8 register tile.
// Dynamic smem: W[k] slice (64KB) + gather tile (33KB, padded) + idx (6.9KB).
// ---------------------------------------------------------------------------
template <bool ADD_RESIDUAL>
__global__ void __launch_bounds__(256, 2)
conv27_kernel(const float* __restrict__ src,
              const int*   __restrict__ nbr,
              const float* __restrict__ W,
              const float* __restrict__ bias,
              const float* __restrict__ residual,
              float*       __restrict__ out) {
    extern __shared__ float smem[];
    float* wsh   = smem;                     // 128*128 floats
    float* gsh   = smem + 128 * 128;         // 64*132 floats
    int*   idxsh = reinterpret_cast<int*>(smem + 128 * 128 + TM * GPITCH); // 64*27

    const int tid  = threadIdx.x;
    const int tx   = tid & 15;           // 0..15  -> cols tx*8..+7
    const int ty   = tid >> 4;           // 0..15  -> rows ty*4..+3
    const int row0 = blockIdx.x * TM;

    // stage neighbor indices for this row tile (layout identical to global)
    for (int l = tid; l < TM * TAPS; l += 256)
        idxsh[l] = nbr[(size_t)row0 * TAPS + l];

    float acc[4][8];
#pragma unroll
    for (int i = 0; i < 4; ++i)
#pragma unroll
        for (int j = 0; j < 8; ++j) acc[i][j] = 0.0f;

    for (int k = 0; k < TAPS; ++k) {
        __syncthreads();   // protect previous iteration's compute reads

        // stage W[k] (128x128)
        const float4* wg = reinterpret_cast<const float4*>(W + (size_t)k * 128 * 128);
        float4* ws4 = reinterpret_cast<float4*>(wsh);
#pragma unroll
        for (int l = 0; l < 16; ++l)
            ws4[l * 256 + tid] = wg[l * 256 + tid];

        // stage gathered features: 64 rows x 128 floats (one warp per row slice)
#pragma unroll
        for (int it = 0; it < 8; ++it) {
            int l  = it * 256 + tid;
            int r  = l >> 5;
            int c4 = (l & 31) << 2;
            int sr = idxsh[r * TAPS + k];
            float4 v = make_float4(0.f, 0.f, 0.f, 0.f);
            if (sr >= 0)
                v = *reinterpret_cast<const float4*>(src + (size_t)sr * C + c4);
            *reinterpret_cast<float4*>(gsh + r * GPITCH + c4) = v;
        }
        __syncthreads();

        // 64x128x128 GEMM accumulate
        const float* gbase = gsh + (ty * 4) * GPITCH;
        const float* wbase = wsh + tx * 8;
#pragma unroll 8
        for (int kk = 0; kk < 128; ++kk) {
            float4 w0 = *reinterpret_cast<const float4*>(wbase + kk * 128);
            float4 w1 = *reinterpret_cast<const float4*>(wbase + kk * 128 + 4);
            float a0 = gbase[kk];
            float a1 = gbase[GPITCH + kk];
            float a2 = gbase[2 * GPITCH + kk];
            float a3 = gbase[3 * GPITCH + kk];
            acc[0][0] = fmaf(a0, w0.x, acc[0][0]); acc[0][1] = fmaf(a0, w0.y, acc[0][1]);
            acc[0][2] = fmaf(a0, w0.z, acc[0][2]); acc[0][3] = fmaf(a0, w0.w, acc[0][3]);
            acc[0][4] = fmaf(a0, w1.x, acc[0][4]); acc[0][5] = fmaf(a0, w1.y, acc[0][5]);
            acc[0][6] = fmaf(a0, w1.z, acc[0][6]); acc[0][7] = fmaf(a0, w1.w, acc[0][7]);
            acc[1][0] = fmaf(a1, w0.x, acc[1][0]); acc[1][1] = fmaf(a1, w0.y, acc[1][1]);
            acc[1][2] = fmaf(a1, w0.z, acc[1][2]); acc[1][3] = fmaf(a1, w0.w, acc[1][3]);
            acc[1][4] = fmaf(a1, w1.x, acc[1][4]); acc[1][5] = fmaf(a1, w1.y, acc[1][5]);
            acc[1][6] = fmaf(a1, w1.z, acc[1][6]); acc[1][7] = fmaf(a1, w1.w, acc[1][7]);
            acc[2][0] = fmaf(a2, w0.x, acc[2][0]); acc[2][1] = fmaf(a2, w0.y, acc[2][1]);
            acc[2][2] = fmaf(a2, w0.z, acc[2][2]); acc[2][3] = fmaf(a2, w0.w, acc[2][3]);
            acc[2][4] = fmaf(a2, w1.x, acc[2][4]); acc[2][5] = fmaf(a2, w1.y, acc[2][5]);
            acc[2][6] = fmaf(a2, w1.z, acc[2][6]); acc[2][7] = fmaf(a2, w1.w, acc[2][7]);
            acc[3][0] = fmaf(a3, w0.x, acc[3][0]); acc[3][1] = fmaf(a3, w0.y, acc[3][1]);
            acc[3][2] = fmaf(a3, w0.z, acc[3][2]); acc[3][3] = fmaf(a3, w0.w, acc[3][3]);
            acc[3][4] = fmaf(a3, w1.x, acc[3][4]); acc[3][5] = fmaf(a3, w1.y, acc[3][5]);
            acc[3][6] = fmaf(a3, w1.z, acc[3][6]); acc[3][7] = fmaf(a3, w1.w, acc[3][7]);
        }
    }

    // epilogue: + bias (+ residual), write out
    float4 bv0 = *reinterpret_cast<const float4*>(bias + tx * 8);
    float4 bv1 = *reinterpret_cast<const float4*>(bias + tx * 8 + 4);
#pragma unroll
    for (int i = 0; i < 4; ++i) {
        int row = row0 + ty * 4 + i;
        size_t off = (size_t)row * C + tx * 8;
        float4 o0 = make_float4(acc[i][0] + bv0.x, acc[i][1] + bv0.y,
                                acc[i][2] + bv0.z, acc[i][3] + bv0.w);
        float4 o1 = make_float4(acc[i][4] + bv1.x, acc[i][5] + bv1.y,
                                acc[i][6] + bv1.z, acc[i][7] + bv1.w);
        if (ADD_RESIDUAL) {
            float4 r0 = *reinterpret_cast<const float4*>(residual + off);
            float4 r1 = *reinterpret_cast<const float4*>(residual + off + 4);
            o0.x += r0.x; o0.y += r0.y; o0.z += r0.z; o0.w += r0.w;
            o1.x += r1.x; o1.y += r1.y; o1.z += r1.z; o1.w += r1.w;
        }
        *reinterpret_cast<float4*>(out + off)     = o0;
        *reinterpret_cast<float4*>(out + off + 4) = o1;
    }
}

// ---------------------------------------------------------------------------
// Host launcher
// ---------------------------------------------------------------------------
extern "C" void kernel_launch(void* const* d_in, const int* in_sizes, int n_in,
                              void* d_out, int out_size) {
    const float* feats = (const float*)d_in[0];
    const float* emb   = (const float*)d_in[1];
    const float* g1    = (const float*)d_in[2];
    const float* b1    = (const float*)d_in[3];
    const float* W1    = (const float*)d_in[4];
    const float* cb1   = (const float*)d_in[5];
    const float* W2    = (const float*)d_in[6];
    const float* cb2   = (const float*)d_in[7];
    const float* embW  = (const float*)d_in[8];
    const float* embb  = (const float*)d_in[9];
    const int*   nbr   = (const int*)d_in[10];
    const int*   bidx  = (const int*)d_in[11];
    float*       out   = (float*)d_out;
    (void)n_in; (void)out_size;

    const int n = in_sizes[0] / C;   // 200000

    const size_t SMEM = (128 * 128 + TM * GPITCH) * sizeof(float)
                      + TM * TAPS * sizeof(int);  // 106,240 B

    cudaFuncSetAttribute(conv27_kernel<false>,
                         cudaFuncAttributeMaxDynamicSharedMemorySize, (int)SMEM);
    cudaFuncSetAttribute(conv27_kernel<true>,
                         cudaFuncAttributeMaxDynamicSharedMemorySize, (int)SMEM);

    float* bufA = nullptr;
    float* bufB = nullptr;
    cudaGetSymbolAddress((void**)&bufA, g_bufA);
    cudaGetSymbolAddress((void**)&bufB, g_bufB);

    // 1. FiLM embedding
    film_kernel<<<4, 256>>>(emb, embW, embb);
    // 2. LN + SiLU -> bufA
    ln_silu_kernel<<<n / 8, 256>>>(feats, g1, b1);
    // 3. conv1: bufA -> bufB
    conv27_kernel<false><<<n / TM, 256, SMEM>>>(bufA, nbr, W1, cb1, nullptr, bufB);
    // 4. LN + FiLM + SiLU: bufB -> bufA
    ln_film_silu_kernel<<<n / 8, 256>>>(bidx);
    // 5. conv2 + residual: bufA -> out
    conv27_kernel<true><<<n / TM, 256, SMEM>>>(bufA, nbr, W2, cb2, feats, out);
}

// round 3
// speedup vs baseline: 5.1510x; 5.1510x over previous
#include <cuda_runtime.h>
#include <cuda_bf16.h>
#include <cstdint>

// ===========================================================================
// SparseResBlock3D — mma.sync tf32 version (base sm_103 target: no tcgen05).
//   film = silu(emb) @ emb_W + emb_b
//   h1   = rna_tf32(silu(LN(feats; g,b)))
//   h2   = sparse_conv27(h1, W1) + b1          [mma.sync tf32, fp32 accum]
//   h3   = rna_tf32(silu(LN(h2)*(1+scale[b]) + shift[b]))
//   out  = sparse_conv27(h3, W2) + b2 + feats  [mma.sync tf32, fp32 accum]
// ===========================================================================

#define NROWS     200000
#define C         128
#define TAPS      27
#define ROWS_CTA  128          // CTA output tile rows
#define NC        108          // K-chunks: 27 taps * 4 (K=32 each)
#define NSTAGE    3
#define STAGE_BYTES 32768      // A(16K) + B(16K)
#define STAGES_OFF  14336      // idx region: 128*27*4 = 13824B, padded
#define DYN_SMEM  (STAGES_OFF + NSTAGE * STAGE_BYTES)   // 112640 B

// ---- scratch (static device globals) ----
__device__ float g_bufA[(size_t)NROWS * C];
__device__ float g_bufB[(size_t)NROWS * C];
__device__ float g_film[4 * 256];
__device__ float g_WT1[(size_t)NC * 4096];   // pre-swizzled, tf32-rounded W^T
__device__ float g_WT2[(size_t)NC * 4096];

// ---------------------------------------------------------------------------
// helpers
// ---------------------------------------------------------------------------
__device__ __forceinline__ float silu_f(float x) { return x / (1.0f + expf(-x)); }

__device__ __forceinline__ float rna_tf32(float x) {
    uint32_t u;
    asm("cvt.rna.tf32.f32 %0, %1;" : "=r"(u) : "f"(x));
    return __uint_as_float(u);
}

__device__ __forceinline__ uint32_t smem_u32(const void* p) {
    uint32_t a;
    asm("{ .reg .u64 t; cvta.to.shared.u64 t, %1; cvt.u32.u64 %0, t; }" : "=r"(a) : "l"(p));
    return a;
}

__device__ __forceinline__ void cp_async16(uint32_t dst, const void* src, int src_bytes) {
    asm volatile("cp.async.cg.shared.global [%0], [%1], 16, %2;"
                 :: "r"(dst), "l"(src), "r"(src_bytes));
}
__device__ __forceinline__ void cp_commit() {
    asm volatile("cp.async.commit_group;");
}
template <int N> __device__ __forceinline__ void cp_wait() {
    asm volatile("cp.async.wait_group %0;" :: "n"(N));
}

__device__ __forceinline__ void ldsm4(uint32_t* r, uint32_t addr) {
    asm volatile("ldmatrix.sync.aligned.m8n8.x4.shared.b16 {%0,%1,%2,%3}, [%4];"
                 : "=r"(r[0]), "=r"(r[1]), "=r"(r[2]), "=r"(r[3]) : "r"(addr));
}

__device__ __forceinline__ void mma_tf32(float* d, const uint32_t* a,
                                         uint32_t b0, uint32_t b1) {
    asm volatile(
        "mma.sync.aligned.m16n8k8.row.col.f32.tf32.tf32.f32 "
        "{%0,%1,%2,%3}, {%4,%5,%6,%7}, {%8,%9}, {%0,%1,%2,%3};"
        : "+f"(d[0]), "+f"(d[1]), "+f"(d[2]), "+f"(d[3])
        : "r"(a[0]), "r"(a[1]), "r"(a[2]), "r"(a[3]), "r"(b0), "r"(b1));
}

// ---------------------------------------------------------------------------
// Kernel 1: FiLM embedding GEMM.  grid=(4), block=256.
// ---------------------------------------------------------------------------
__global__ void film_kernel(const float* __restrict__ emb,
                            const float* __restrict__ embW,
                            const float* __restrict__ embb) {
    __shared__ float s[512];
    int b = blockIdx.x;
    int c = threadIdx.x;
    for (int e = c; e < 512; e += 256) s[e] = silu_f(emb[b * 512 + e]);
    __syncthreads();
    float acc = embb[c];
#pragma unroll 8
    for (int e = 0; e < 512; ++e) acc = fmaf(s[e], embW[e * 256 + c], acc);
    g_film[b * 256 + c] = (c < 128) ? (1.0f + acc) : acc;
}

// ---------------------------------------------------------------------------
// Kernel 2: LN(gamma,beta) + SiLU + tf32-round -> g_bufA.
// ---------------------------------------------------------------------------
__global__ void ln_silu_kernel(const float* __restrict__ x,
                               const float* __restrict__ gamma,
                               const float* __restrict__ beta) {
    int row  = blockIdx.x * 8 + (threadIdx.x >> 5);
    int lane = threadIdx.x & 31;
    float4 v = reinterpret_cast<const float4*>(x + (size_t)row * C)[lane];
    float s  = v.x + v.y + v.z + v.w;
    float ss = v.x * v.x + v.y * v.y + v.z * v.z + v.w * v.w;
#pragma unroll
    for (int o = 16; o > 0; o >>= 1) {
        s  += __shfl_xor_sync(0xffffffffu, s, o);
        ss += __shfl_xor_sync(0xffffffffu, ss, o);
    }
    float mu  = s * (1.0f / 128.0f);
    float inv = rsqrtf(ss * (1.0f / 128.0f) - mu * mu + 1e-6f);
    float4 g  = reinterpret_cast<const float4*>(gamma)[lane];
    float4 be = reinterpret_cast<const float4*>(beta)[lane];
    float4 y;
    y.x = rna_tf32(silu_f((v.x - mu) * inv * g.x + be.x));
    y.y = rna_tf32(silu_f((v.y - mu) * inv * g.y + be.y));
    y.z = rna_tf32(silu_f((v.z - mu) * inv * g.z + be.z));
    y.w = rna_tf32(silu_f((v.w - mu) * inv * g.w + be.w));
    reinterpret_cast<float4*>(g_bufA + (size_t)row * C)[lane] = y;
}

// ---------------------------------------------------------------------------
// Kernel 4: LN(no affine) + FiLM + SiLU + tf32-round : g_bufB -> g_bufA.
// ---------------------------------------------------------------------------
__global__ void ln_film_silu_kernel(const int* __restrict__ batch_idx) {
    int row  = blockIdx.x * 8 + (threadIdx.x >> 5);
    int lane = threadIdx.x & 31;
    float4 v = reinterpret_cast<const float4*>(g_bufB + (size_t)row * C)[lane];
    float s  = v.x + v.y + v.z + v.w;
    float ss = v.x * v.x + v.y * v.y + v.z * v.z + v.w * v.w;
#pragma unroll
    for (int o = 16; o > 0; o >>= 1) {
        s  += __shfl_xor_sync(0xffffffffu, s, o);
        ss += __shfl_xor_sync(0xffffffffu, ss, o);
    }
    float mu  = s * (1.0f / 128.0f);
    float inv = rsqrtf(ss * (1.0f / 128.0f) - mu * mu + 1e-6f);
    int b = batch_idx[row];
    float4 sc = *reinterpret_cast<const float4*>(&g_film[b * 256 + lane * 4]);
    float4 sh = *reinterpret_cast<const float4*>(&g_film[b * 256 + 128 + lane * 4]);
    float4 y;
    y.x = rna_tf32(silu_f((v.x - mu) * inv * sc.x + sh.x));
    y.y = rna_tf32(silu_f((v.y - mu) * inv * sc.y + sh.y));
    y.z = rna_tf32(silu_f((v.z - mu) * inv * sc.z + sh.z));
    y.w = rna_tf32(silu_f((v.w - mu) * inv * sc.w + sh.w));
    reinterpret_cast<float4*>(g_bufA + (size_t)row * C)[lane] = y;
}

// ---------------------------------------------------------------------------
// Weight prep: transpose to [N,K], tf32-round, swizzle-pack.
// grid = NC (108), block = 256. Chunk c: tap k=c/4, K-range q=c%4 (32 floats).
// Chunk tile = [128 n rows][32 K floats = 128B], XOR-swizzled, 16KB contiguous.
// ---------------------------------------------------------------------------
__global__ void wprep_kernel(const float* __restrict__ W, float* __restrict__ WT) {
    int c = blockIdx.x;
    int k = c >> 2, q = c & 3;
    for (int e = threadIdx.x; e < 4096; e += 256) {
        int nn = e >> 5, w = e & 31;
        float v = rna_tf32(W[((size_t)k * 128 + q * 32 + w) * 128 + nn]);
        int off = nn * 128 + w * 4;
        WT[(size_t)c * 4096 + ((off ^ ((off >> 3) & 0x70)) >> 2)] = v;
    }
}

// ---------------------------------------------------------------------------
// mma.sync tf32 sparse conv. 256 threads (8 warps), CTA 128 rows x 128 cols.
// Warp tile m32 x n64 (4 m-warps x 2 n-warps). 3-stage cp.async pipeline over
// 108 K-chunks (27 taps x K=32).
// ---------------------------------------------------------------------------
template <bool ADD_RESIDUAL>
__global__ void __launch_bounds__(256, 2)
conv_mma_kernel(const float* __restrict__ src,
                const int*   __restrict__ nbr,
                const float* __restrict__ WT,
                const float* __restrict__ bias,
                const float* __restrict__ residual,
                float*       __restrict__ out,
                int n) {
    extern __shared__ char dsm[];
    int* idxsh = reinterpret_cast<int*>(dsm);

    const int tid  = threadIdx.x;
    const int wid  = tid >> 5;
    const int lane = tid & 31;
    const int row0 = blockIdx.x * ROWS_CTA;
    const uint32_t dsm_u32 = smem_u32(dsm);

    // --- stage neighbor indices (tail rows forced invalid) ---
    for (int l = tid; l < ROWS_CTA * TAPS; l += 256) {
        int gr = row0 + l / TAPS;
        idxsh[l] = (gr < n) ? nbr[(size_t)gr * TAPS + (l % TAPS)] : -1;
    }
    __syncthreads();

    // loader constants: 2 threads per row, 64B each
    const int a_row  = tid >> 1;
    const int a_half = tid & 1;

    auto load_chunk = [&](int c) {
        int st = c % NSTAGE;
        uint32_t sb = dsm_u32 + STAGES_OFF + st * STAGE_BYTES;
        int k = c >> 2, q = c & 3;
        int idx = idxsh[a_row * TAPS + k];
        const float* srow = src + (size_t)(idx < 0 ? 0 : idx) * C + q * 32 + a_half * 16;
        int bytes = (idx < 0) ? 0 : 16;
#pragma unroll
        for (int i = 0; i < 4; ++i) {
            int off = a_row * 128 + a_half * 64 + i * 16;
            cp_async16(sb + (off ^ ((off >> 3) & 0x70)), srow + i * 4, bytes);
        }
        const float* bsrc = WT + (size_t)c * 4096 + tid * 16;
        uint32_t bd = sb + 16384 + tid * 64;
#pragma unroll
        for (int i = 0; i < 4; ++i) cp_async16(bd + i * 16, bsrc + i * 4, 16);
        cp_commit();
    };

    // --- warp tiling + ldmatrix lane address components ---
    const int wm = wid & 3;          // m-warp (rows 32*wm)
    const int wn = wid >> 2;         // n-warp (cols 64*wn)

    // A fragment lanes: row = 32*wm + 16*mt + (lane&15), k-half = lane>>4
    uint32_t a_rowoff[2];
    int      a_ph[2];
#pragma unroll
    for (int mt = 0; mt < 2; ++mt) {
        int r = 32 * wm + 16 * mt + (lane & 15);
        a_rowoff[mt] = r * 128;
        a_ph[mt]     = r & 7;
    }
    const int a_kbh = lane >> 4;     // 0/1 -> k0-3 / k4-7

    // B fragment lanes: row = 64*wn + 16*np + (lane&7) + ((lane>>4)<<3),
    //                   k-half = (lane>>3)&1
    uint32_t b_rowoff[4];
    int      b_ph[4];
#pragma unroll
    for (int np = 0; np < 4; ++np) {
        int r = 64 * wn + 16 * np + (lane & 7) + ((lane >> 4) << 3);
        b_rowoff[np] = r * 128;
        b_ph[np]     = r & 7;
    }
    const int b_kbh = (lane >> 3) & 1;

    float d[2][8][4];
#pragma unroll
    for (int mt = 0; mt < 2; ++mt)
#pragma unroll
        for (int nt = 0; nt < 8; ++nt)
#pragma unroll
            for (int j = 0; j < 4; ++j) d[mt][nt][j] = 0.0f;

    // prologue
    load_chunk(0);
    load_chunk(1);

    for (int c = 0; c < NC; ++c) {
        if (c < NC - 1) cp_wait<1>(); else cp_wait<0>();
        __syncthreads();

        uint32_t sb    = dsm_u32 + STAGES_OFF + (c % NSTAGE) * STAGE_BYTES;
        uint32_t abase = sb;
        uint32_t bbase = sb + 16384;

#pragma unroll
        for (int ks = 0; ks < 4; ++ks) {
            uint32_t a0[4], a1[4];
            ldsm4(a0, abase + a_rowoff[0] + ((((ks << 1) | a_kbh) ^ a_ph[0]) << 4));
            ldsm4(a1, abase + a_rowoff[1] + ((((ks << 1) | a_kbh) ^ a_ph[1]) << 4));
#pragma unroll
            for (int np = 0; np < 4; ++np) {
                uint32_t b[4];
                ldsm4(b, bbase + b_rowoff[np] + ((((ks << 1) | b_kbh) ^ b_ph[np]) << 4));
                mma_tf32(d[0][2 * np],     a0, b[0], b[1]);
                mma_tf32(d[0][2 * np + 1], a0, b[2], b[3]);
                mma_tf32(d[1][2 * np],     a1, b[0], b[1]);
                mma_tf32(d[1][2 * np + 1], a1, b[2], b[3]);
            }
        }
        __syncthreads();
        if (c + 2 < NC) load_chunk(c + 2);
    }

    // --- epilogue ---
    const int qr = lane >> 2;            // 0..7
    const int qc = (lane & 3) * 2;       // 0,2,4,6
#pragma unroll
    for (int mt = 0; mt < 2; ++mt) {
#pragma unroll
        for (int nt = 0; nt < 8; ++nt) {
            int gc = 64 * wn + 8 * nt + qc;
            float2 bb = *reinterpret_cast<const float2*>(bias + gc);
            int gr0 = row0 + 32 * wm + 16 * mt + qr;
            int gr1 = gr0 + 8;
            if (gr0 < n) {
                float2 o = make_float2(d[mt][nt][0] + bb.x, d[mt][nt][1] + bb.y);
                size_t off = (size_t)gr0 * C + gc;
                if (ADD_RESIDUAL) {
                    float2 r = *reinterpret_cast<const float2*>(residual + off);
                    o.x += r.x; o.y += r.y;
                }
                *reinterpret_cast<float2*>(out + off) = o;
            }
            if (gr1 < n) {
                float2 o = make_float2(d[mt][nt][2] + bb.x, d[mt][nt][3] + bb.y);
                size_t off = (size_t)gr1 * C + gc;
                if (ADD_RESIDUAL) {
                    float2 r = *reinterpret_cast<const float2*>(residual + off);
                    o.x += r.x; o.y += r.y;
                }
                *reinterpret_cast<float2*>(out + off) = o;
            }
        }
    }
}

// ---------------------------------------------------------------------------
// Host launcher
// ---------------------------------------------------------------------------
extern "C" void kernel_launch(void* const* d_in, const int* in_sizes, int n_in,
                              void* d_out, int out_size) {
    const float* feats = (const float*)d_in[0];
    const float* emb   = (const float*)d_in[1];
    const float* g1    = (const float*)d_in[2];
    const float* b1    = (const float*)d_in[3];
    const float* W1    = (const float*)d_in[4];
    const float* cb1   = (const float*)d_in[5];
    const float* W2    = (const float*)d_in[6];
    const float* cb2   = (const float*)d_in[7];
    const float* embW  = (const float*)d_in[8];
    const float* embb  = (const float*)d_in[9];
    const int*   nbr   = (const int*)d_in[10];
    const int*   bidx  = (const int*)d_in[11];
    float*       out   = (float*)d_out;
    (void)n_in; (void)out_size;

    const int n = in_sizes[0] / C;                        // 200000
    const int nblk = (n + ROWS_CTA - 1) / ROWS_CTA;       // 1563

    cudaFuncSetAttribute(conv_mma_kernel<false>,
                         cudaFuncAttributeMaxDynamicSharedMemorySize, DYN_SMEM);
    cudaFuncSetAttribute(conv_mma_kernel<true>,
                         cudaFuncAttributeMaxDynamicSharedMemorySize, DYN_SMEM);

    float *bufA, *bufB, *wt1, *wt2;
    cudaGetSymbolAddress((void**)&bufA, g_bufA);
    cudaGetSymbolAddress((void**)&bufB, g_bufB);
    cudaGetSymbolAddress((void**)&wt1, g_WT1);
    cudaGetSymbolAddress((void**)&wt2, g_WT2);

    film_kernel<<<4, 256>>>(emb, embW, embb);
    wprep_kernel<<<NC, 256>>>(W1, wt1);
    wprep_kernel<<<NC, 256>>>(W2, wt2);
    ln_silu_kernel<<<n / 8, 256>>>(feats, g1, b1);
    conv_mma_kernel<false><<<nblk, 256, DYN_SMEM>>>(bufA, nbr, wt1, cb1, nullptr, bufB, n);
    ln_film_silu_kernel<<<n / 8, 256>>>(bidx);
    conv_mma_kernel<true><<<nblk, 256, DYN_SMEM>>>(bufA, nbr, wt2, cb2, feats, out, n);
}